// round 15
// baseline (speedup 1.0000x reference)
#include <cuda_runtime.h>
#include <cuda_fp16.h>
#include <cstdint>

#define Ss 2048
#define Dd 64
constexpr int BH  = 32;
constexpr int QT  = 64;            // q rows per CTA
constexpr int KT  = 128;           // k cols per tile
constexpr int NTH = 256;
constexpr int NT  = Ss / KT;       // 16
constexpr long long OUT_ELEMS = (long long)BH * Ss * Dd;
constexpr long long ATT_ELEMS = (long long)BH * Ss * (long long)Ss;

// static device scratch
__device__ __align__(256) __half g_qh[(size_t)BH * Ss * Dd];   // pre-scaled by log2e/8
__device__ __align__(256) __half g_kh[(size_t)BH * Ss * Dd];
__device__ __align__(256) __half g_vh[(size_t)BH * Ss * Dd];
__device__ __align__(256) uint32_t g_mb[(size_t)2 * Ss * Ss / 32];   // bit-packed mask
__device__ __align__(256) uint32_t g_u32[(size_t)ATT_ELEMS / 2];     // u relay, fragment layout
__device__ __align__(256) float g_rs[(size_t)BH * Ss];               // 1/rowsum

// P1 smem
constexpr int OFF_RED = 0;
constexpr int OFF_Q   = 1024;
constexpr int KSTG    = 128 * 144;                // 18432
constexpr int OFF_K   = 10240;                    // 2 stages -> 47104
constexpr int SMEM_P1 = 47104;                    // 3 CTAs/SM
// P2 smem
constexpr int OFF_V   = 1024;                     // 2 stages -> 37888
constexpr int SMEM_P2 = 1024 + 3 * 64 * 66 * 4;   // 51712 (o-combine overlay dominates)

__device__ __forceinline__ uint32_t smem_u32(const void* p) {
    uint32_t a;
    asm("{ .reg .u64 t; cvta.to.shared.u64 t, %1; cvt.u32.u64 %0, t; }" : "=r"(a) : "l"(p));
    return a;
}
__device__ __forceinline__ void ldsm4(uint32_t r[4], uint32_t a) {
    asm volatile("ldmatrix.sync.aligned.m8n8.x4.shared.b16 {%0,%1,%2,%3}, [%4];"
                 : "=r"(r[0]), "=r"(r[1]), "=r"(r[2]), "=r"(r[3]) : "r"(a) : "memory");
}
__device__ __forceinline__ void ldsm4t(uint32_t r[4], uint32_t a) {
    asm volatile("ldmatrix.sync.aligned.m8n8.x4.trans.shared.b16 {%0,%1,%2,%3}, [%4];"
                 : "=r"(r[0]), "=r"(r[1]), "=r"(r[2]), "=r"(r[3]) : "r"(a) : "memory");
}
__device__ __forceinline__ void mma16816(float c[4], const uint32_t a[4], uint32_t b0, uint32_t b1) {
    asm volatile(
        "mma.sync.aligned.m16n8k16.row.col.f32.f16.f16.f32 "
        "{%0,%1,%2,%3}, {%4,%5,%6,%7}, {%8,%9}, {%0,%1,%2,%3};"
        : "+f"(c[0]), "+f"(c[1]), "+f"(c[2]), "+f"(c[3])
        : "r"(a[0]), "r"(a[1]), "r"(a[2]), "r"(a[3]), "r"(b0), "r"(b1));
}
__device__ __forceinline__ uint32_t packh2(float x, float y) {
    __half2 h = __floats2half2_rn(x, y);
    return *(uint32_t*)&h;
}
__device__ __forceinline__ float ex2f(float x) {
    float r; asm("ex2.approx.f32 %0, %1;" : "=f"(r) : "f"(x)); return r;
}
#define CPA16(dst, src) asm volatile("cp.async.cg.shared.global [%0], [%1], 16;" :: "r"(dst), "l"(src))
#define CP_COMMIT()     asm volatile("cp.async.commit_group;" ::: "memory")
#define CP_WAIT0()      asm volatile("cp.async.wait_group 0;" ::: "memory")
#define STG64CS(p, x, y) \
    asm volatile("st.global.cs.v2.f32 [%0], {%1,%2};" :: "l"(p), "f"(x), "f"(y) : "memory")

constexpr int QKV_BLOCKS  = 3 * (BH * Ss * Dd / 4) / 256;       // 12288
constexpr int MBIT_BLOCKS = (2 * Ss * Ss / 32) / 256;           // 1024
constexpr float QSCALE = 0.18033688011112042f;                  // log2(e)/8

__global__ void __launch_bounds__(256) cvt_all(const float* __restrict__ Q,
                                               const float* __restrict__ K,
                                               const float* __restrict__ V,
                                               const int* __restrict__ M)
{
    if (blockIdx.x < QKV_BLOCKS) {
        const int n4 = BH * Ss * Dd / 4;
        int id = blockIdx.x * 256 + threadIdx.x;
        const float* src; __half* dst; float s;
        int i = id;
        if (id < n4)          { src = Q; dst = g_qh; s = QSCALE; }
        else if (id < 2 * n4) { src = K; dst = g_kh; s = 1.f; i -= n4; }
        else                  { src = V; dst = g_vh; s = 1.f; i -= 2 * n4; }
        float4 v = ((const float4*)src)[i];
        uint2 u; u.x = packh2(v.x * s, v.y * s); u.y = packh2(v.z * s, v.w * s);
        ((uint2*)dst)[i] = u;
    } else {
        int gid = (blockIdx.x - QKV_BLOCKS) * 256 + threadIdx.x;
        const int4* mp = (const int4*)M + (size_t)gid * 8;
        uint32_t bits = 0;
        #pragma unroll
        for (int j = 0; j < 8; j++) {
            int4 m = mp[j];
            bits |= (m.x ? 1u : 0u) << (4 * j);
            bits |= (m.y ? 1u : 0u) << (4 * j + 1);
            bits |= (m.z ? 1u : 0u) << (4 * j + 2);
            bits |= (m.w ? 1u : 0u) << (4 * j + 3);
        }
        g_mb[gid] = bits;
    }
}

extern __shared__ __align__(16) char sm[];

// ================= PASS 1 kernel: row sums + u relay =================
#define P1_BODY(T, CUR, NXT) do {                                          \
    if ((T) + 1 < NT) {                                                    \
        CPA16(kdst##NXT,         kpre);                                    \
        CPA16(kdst##NXT +  4608, kpre + 2048);                             \
        CPA16(kdst##NXT +  9216, kpre + 4096);                             \
        CPA16(kdst##NXT + 13824, kpre + 6144);                             \
        CP_COMMIT();                                                       \
        kpre += (size_t)KT * Dd;                                           \
        mn0 = __ldg(mr0 + 2 * ((T) + 1));                                  \
        mn1 = __ldg(mr1 + 2 * ((T) + 1));                                  \
    }                                                                      \
    _Pragma("unroll") for (int ch = 0; ch < 2; ch++) {                     \
        float c4[4][4];                                                    \
        _Pragma("unroll") for (int j = 0; j < 4; j++) {                    \
            c4[j][0] = 0.f; c4[j][1] = 0.f; c4[j][2] = 0.f; c4[j][3] = 0.f; } \
        _Pragma("unroll") for (int kc = 0; kc < 4; kc++)                   \
            _Pragma("unroll") for (int j = 0; j < 2; j++) {                \
                uint32_t bf[4];                                            \
                ldsm4(bf, kfr##CUR + (2 * ch + j) * 2304 + kc * 32);       \
                mma16816(c4[2 * j],     aQ[kc], bf[0], bf[1]);             \
                mma16816(c4[2 * j + 1], aQ[kc], bf[2], bf[3]);             \
            }                                                              \
        uint32_t ul[4], uh[4];                                             \
        _Pragma("unroll") for (int j = 0; j < 4; j++) {                    \
            const int p = 8 * (4 * ch + j) + 2 * tg;                       \
            uint32_t b0 = (uint32_t)(mc0 >> p), b1 = (uint32_t)(mc1 >> p); \
            float u0 = (b0 & 1u) ? ex2f(c4[j][0]) : 0.f;                   \
            float u1 = (b0 & 2u) ? ex2f(c4[j][1]) : 0.f;                   \
            float u2 = (b1 & 1u) ? ex2f(c4[j][2]) : 0.f;                   \
            float u3 = (b1 & 2u) ? ex2f(c4[j][3]) : 0.f;                   \
            rs0 += u0 + u1; rs1 += u2 + u3;                                \
            ul[j] = packh2(u0, u1); uh[j] = packh2(u2, u3);                \
        }                                                                  \
        *(uint4*)(ut + (2 * ch) * 1024)     = make_uint4(ul[0], uh[0], ul[1], uh[1]); \
        *(uint4*)(ut + (2 * ch + 1) * 1024) = make_uint4(ul[2], uh[2], ul[3], uh[3]); \
    }                                                                      \
    ut += 4096;                                                            \
    mc0 = mn0; mc1 = mn1;                                                  \
    if ((T) + 1 < NT) { CP_WAIT0(); __syncthreads(); }                     \
} while (0)

__global__ void __launch_bounds__(NTH, 3)
attn_p1()
{
    const int tid  = threadIdx.x;
    const int lane = tid & 31;
    const int warp = tid >> 5;
    const int g    = lane >> 2;
    const int tg   = lane & 3;
    const int lm   = lane >> 3;
    const int ll   = lane & 7;
    const int rgrp = warp & 3;
    const int h    = warp >> 2;

    const int qblk = blockIdx.x;
    const int q0 = qblk * QT;
    const int bh = blockIdx.y;
    const int b  = bh >> 4;

    const uint32_t smb = smem_u32(sm);
    float* srows = (float*)(sm + OFF_RED);

    const __half* qsrc = g_qh + ((size_t)bh * Ss + q0) * Dd;
    const __half* ksrc = g_kh + (size_t)bh * Ss * Dd;

    const int r0 = rgrp * 16 + g;
    const int r1 = r0 + 8;

    const unsigned long long* mb64 = (const unsigned long long*)g_mb;
    const unsigned long long* mr0 = mb64 + ((size_t)b * Ss + q0 + r0) * 32 + h;
    const unsigned long long* mr1 = mr0 + 8 * 32;

    uint32_t* ut = g_u32 + (((size_t)bh * 32 + qblk) * 16) * 4096 + tid * 4;

    const int lr_ = tid >> 3, lc = tid & 7;
    const uint32_t kdstA = smb + OFF_K + lr_ * 144 + lc * 16;
    const uint32_t kdstB = kdstA + KSTG;
    const __half* ksrcT = ksrc + lr_ * 64 + lc * 8;

    const uint32_t qfr  = smb + OFF_Q + (uint32_t)((rgrp * 16 + (lm & 1) * 8 + ll) * 144 + (lm >> 1) * 16);
    const uint32_t kfrA = smb + OFF_K + (uint32_t)((h * 64 + (lm >> 1) * 8 + ll) * 144 + (lm & 1) * 16);
    const uint32_t kfrB = kfrA + KSTG;

    CPA16(smb + OFF_Q + lr_ * 144 + lc * 16, qsrc + lr_ * 64 + lc * 8);
    CPA16(smb + OFF_Q + (lr_ + 32) * 144 + lc * 16, qsrc + (lr_ + 32) * 64 + lc * 8);
    CPA16(kdstA,         ksrcT);
    CPA16(kdstA +  4608, ksrcT + 2048);
    CPA16(kdstA +  9216, ksrcT + 4096);
    CPA16(kdstA + 13824, ksrcT + 6144);
    CP_COMMIT();
    unsigned long long mc0 = __ldg(mr0), mc1 = __ldg(mr1), mn0 = 0, mn1 = 0;
    CP_WAIT0(); __syncthreads();

    uint32_t aQ[4][4];
    #pragma unroll
    for (int kc = 0; kc < 4; kc++) ldsm4(aQ[kc], qfr + kc * 32);

    float rs0 = 0.f, rs1 = 0.f;
    {
        const __half* kpre = ksrcT + (size_t)KT * Dd;
        #pragma unroll 1
        for (int t2 = 0; t2 < NT; t2 += 2) {
            P1_BODY(t2,     A, B);
            P1_BODY(t2 + 1, B, A);
        }
    }

    rs0 += __shfl_xor_sync(0xffffffffu, rs0, 1); rs0 += __shfl_xor_sync(0xffffffffu, rs0, 2);
    rs1 += __shfl_xor_sync(0xffffffffu, rs1, 1); rs1 += __shfl_xor_sync(0xffffffffu, rs1, 2);
    if (tg == 0) { srows[h * 64 + r0] = rs0; srows[h * 64 + r1] = rs1; }
    __syncthreads();
    if (tid < 64) {
        float s = srows[tid] + srows[64 + tid];
        g_rs[(size_t)bh * Ss + q0 + tid] = (s > 0.f) ? (1.0f / s) : 0.f;
    }
}

// ================= PASS 2 kernel: PV + scaled att (32-row warp tiles) =================
#define P2_BODY(T, CUR, NXT) do {                                          \
    uint4 ua00 = __ldg((const uint4*)(ubt + u00));                         \
    uint4 ua01 = __ldg((const uint4*)(ubt + u01));                         \
    uint4 ua10 = __ldg((const uint4*)(ubt + u10));                         \
    uint4 ua11 = __ldg((const uint4*)(ubt + u11));                         \
    ubt += 16384;                                                          \
    if ((T) + 1 < NT) {                                                    \
        CPA16(vdst##NXT,         vpre);                                    \
        CPA16(vdst##NXT +  4608, vpre + 2048);                             \
        CPA16(vdst##NXT +  9216, vpre + 4096);                             \
        CPA16(vdst##NXT + 13824, vpre + 6144);                             \
        CP_COMMIT();                                                       \
        vpre += (size_t)KT * Dd;                                           \
    }                                                                      \
    _Pragma("unroll") for (int ks = 0; ks < 2; ks++) {                     \
        uint32_t a0[4], a1[4];                                             \
        if (ks == 0) { a0[0]=ua00.x; a0[1]=ua00.y; a0[2]=ua00.z; a0[3]=ua00.w; \
                       a1[0]=ua10.x; a1[1]=ua10.y; a1[2]=ua10.z; a1[3]=ua10.w; } \
        else         { a0[0]=ua01.x; a0[1]=ua01.y; a0[2]=ua01.z; a0[3]=ua01.w; \
                       a1[0]=ua11.x; a1[1]=ua11.y; a1[2]=ua11.z; a1[3]=ua11.w; } \
        _Pragma("unroll") for (int np = 0; np < 4; np++) {                 \
            uint32_t bf[4];                                                \
            ldsm4t(bf, vfr##CUR + (2 * hp + ks) * 2304 + np * 32);         \
            mma16816(o[0][2 * np],     a0, bf[0], bf[1]);                  \
            mma16816(o[0][2 * np + 1], a0, bf[2], bf[3]);                  \
            mma16816(o[1][2 * np],     a1, bf[0], bf[1]);                  \
            mma16816(o[1][2 * np + 1], a1, bf[2], bf[3]);                  \
        }                                                                  \
    }                                                                      \
    if (ar00) {                                                            \
        float2 f;                                                          \
        f = __half22float2(*(__half2*)&ua00.x); STG64CS(ar00,      f.x * rv00, f.y * rv00); \
        f = __half22float2(*(__half2*)&ua00.y); STG64CS(ar01,      f.x * rv01, f.y * rv01); \
        f = __half22float2(*(__half2*)&ua00.z); STG64CS(ar00 +  8, f.x * rv00, f.y * rv00); \
        f = __half22float2(*(__half2*)&ua00.w); STG64CS(ar01 +  8, f.x * rv01, f.y * rv01); \
        f = __half22float2(*(__half2*)&ua01.x); STG64CS(ar00 + 16, f.x * rv00, f.y * rv00); \
        f = __half22float2(*(__half2*)&ua01.y); STG64CS(ar01 + 16, f.x * rv01, f.y * rv01); \
        f = __half22float2(*(__half2*)&ua01.z); STG64CS(ar00 + 24, f.x * rv00, f.y * rv00); \
        f = __half22float2(*(__half2*)&ua01.w); STG64CS(ar01 + 24, f.x * rv01, f.y * rv01); \
        f = __half22float2(*(__half2*)&ua10.x); STG64CS(ar10,      f.x * rv10, f.y * rv10); \
        f = __half22float2(*(__half2*)&ua10.y); STG64CS(ar11,      f.x * rv11, f.y * rv11); \
        f = __half22float2(*(__half2*)&ua10.z); STG64CS(ar10 +  8, f.x * rv10, f.y * rv10); \
        f = __half22float2(*(__half2*)&ua10.w); STG64CS(ar11 +  8, f.x * rv11, f.y * rv11); \
        f = __half22float2(*(__half2*)&ua11.x); STG64CS(ar10 + 16, f.x * rv10, f.y * rv10); \
        f = __half22float2(*(__half2*)&ua11.y); STG64CS(ar11 + 16, f.x * rv11, f.y * rv11); \
        f = __half22float2(*(__half2*)&ua11.z); STG64CS(ar10 + 24, f.x * rv10, f.y * rv10); \
        f = __half22float2(*(__half2*)&ua11.w); STG64CS(ar11 + 24, f.x * rv11, f.y * rv11); \
        ar00 += KT; ar01 += KT; ar10 += KT; ar11 += KT;                    \
    }                                                                      \
    if ((T) + 1 < NT) { CP_WAIT0(); __syncthreads(); }                     \
} while (0)

__global__ void __launch_bounds__(NTH, 2)
attn_p2(float* __restrict__ out, float* __restrict__ att)
{
    const int tid  = threadIdx.x;
    const int lane = tid & 31;
    const int warp = tid >> 5;
    const int g    = lane >> 2;
    const int tg   = lane & 3;
    const int lm   = lane >> 3;
    const int ll   = lane & 7;
    const int rg   = warp & 1;         // 32-row group
    const int hp   = warp >> 1;        // 32-col k group (0..3)

    const int qblk = blockIdx.x;
    const int q0 = qblk * QT;
    const int bh = blockIdx.y;

    const uint32_t smb = smem_u32(sm);

    const __half* vsrc = g_vh + (size_t)bh * Ss * Dd;
    float* attg = att ? (att + (size_t)bh * Ss * (size_t)Ss) : nullptr;

    // V cp.async + fragment bases
    const int lr_ = tid >> 3, lc = tid & 7;
    const uint32_t vdstA = smb + OFF_V + lr_ * 144 + lc * 16;
    const uint32_t vdstB = vdstA + KSTG;
    const __half* vsrcT = vsrc + lr_ * 64 + lc * 8;
    const uint32_t vfrA = smb + OFF_V + (uint32_t)(((lm & 1) * 8 + ll) * 144 + (lm >> 1) * 16);
    const uint32_t vfrB = vfrA + KSTG;

    // relay addresses (P1 fragment layout): slot = 2*(hp&1)+ks, tidP1 = (hp>>1)*128 + (2rg+mi)*32 + 4g+tg
    const char* ubt = (const char*)(g_u32 + (((size_t)bh * 32 + qblk) * 16) * 4096);
    const int tp0 = (hp >> 1) * 128 + rg * 64 + g * 4 + tg;
    const uint32_t u00 = (uint32_t)((2 * (hp & 1)) * 4096 + tp0 * 16);   // mi=0, ks=0
    const uint32_t u01 = u00 + 4096;                                     // mi=0, ks=1
    const uint32_t u10 = u00 + 512;                                      // mi=1, ks=0
    const uint32_t u11 = u01 + 512;                                      // mi=1, ks=1

    // reciprocals for this thread's 4 rows
    const int R0 = rg * 32;
    const float* rsb = g_rs + (size_t)bh * Ss + q0 + R0 + g;
    const float rv00 = __ldg(rsb);
    const float rv01 = __ldg(rsb + 8);
    const float rv10 = __ldg(rsb + 16);
    const float rv11 = __ldg(rsb + 24);

    // att row pointers (cols base 32hp + 2tg)
    float *ar00 = nullptr, *ar01 = nullptr, *ar10 = nullptr, *ar11 = nullptr;
    if (attg) {
        float* base = attg + (size_t)(q0 + R0 + g) * Ss + 32 * hp + 2 * tg;
        ar00 = base;
        ar01 = base + (size_t)8 * Ss;
        ar10 = base + (size_t)16 * Ss;
        ar11 = base + (size_t)24 * Ss;
    }

    float o[2][8][4];
    #pragma unroll
    for (int mi = 0; mi < 2; mi++)
        #pragma unroll
        for (int j = 0; j < 8; j++) { o[mi][j][0] = 0.f; o[mi][j][1] = 0.f; o[mi][j][2] = 0.f; o[mi][j][3] = 0.f; }

    // prologue: V0 -> stage A
    CPA16(vdstA,         vsrcT);
    CPA16(vdstA +  4608, vsrcT + 2048);
    CPA16(vdstA +  9216, vsrcT + 4096);
    CPA16(vdstA + 13824, vsrcT + 6144);
    CP_COMMIT(); CP_WAIT0(); __syncthreads();

    {
        const __half* vpre = vsrcT + (size_t)KT * Dd;
        #pragma unroll 1
        for (int t2 = 0; t2 < NT; t2 += 2) {
            P2_BODY(t2,     A, B);
            P2_BODY(t2 + 1, B, A);
        }
    }

    // ---- combine 4 k-groups of O via smem, scale by rinv, write ----
    __syncthreads();
    float* ost = (float*)(sm + 1024);              // 3 x [64][66]
    if (hp > 0) {
        float* sh = ost + (hp - 1) * 64 * 66;
        #pragma unroll
        for (int mi = 0; mi < 2; mi++) {
            const int ra = R0 + mi * 16 + g;
            #pragma unroll
            for (int j = 0; j < 8; j++) {
                *(float2*)&sh[ra * 66 + 8 * j + 2 * tg]       = make_float2(o[mi][j][0], o[mi][j][1]);
                *(float2*)&sh[(ra + 8) * 66 + 8 * j + 2 * tg] = make_float2(o[mi][j][2], o[mi][j][3]);
            }
        }
    }
    __syncthreads();
    if (out && hp == 0) {
        #pragma unroll
        for (int mi = 0; mi < 2; mi++) {
            const int ra = R0 + mi * 16 + g;
            const float rva = (mi == 0) ? rv00 : rv10;
            const float rvb = (mi == 0) ? rv01 : rv11;
            float* og0 = out + ((size_t)bh * Ss + q0 + ra) * Dd;
            float* og1 = og0 + (size_t)8 * Dd;
            #pragma unroll
            for (int j = 0; j < 8; j++) {
                float a0 = o[mi][j][0], a1 = o[mi][j][1], a2 = o[mi][j][2], a3 = o[mi][j][3];
                #pragma unroll
                for (int p = 0; p < 3; p++) {
                    float2 s0 = *(float2*)&ost[p * 64 * 66 + ra * 66 + 8 * j + 2 * tg];
                    float2 s1 = *(float2*)&ost[p * 64 * 66 + (ra + 8) * 66 + 8 * j + 2 * tg];
                    a0 += s0.x; a1 += s0.y; a2 += s1.x; a3 += s1.y;
                }
                *(float2*)(og0 + 8 * j + 2 * tg) = make_float2(a0 * rva, a1 * rva);
                *(float2*)(og1 + 8 * j + 2 * tg) = make_float2(a2 * rvb, a3 * rvb);
            }
        }
    }
}

extern "C" void kernel_launch(void* const* d_in, const int* in_sizes, int n_in,
                              void* d_out, int out_size)
{
    (void)in_sizes; (void)n_in;
    const float* Q = (const float*)d_in[0];
    const float* K = (const float*)d_in[1];
    const float* V = (const float*)d_in[2];
    const int*   M = (const int*)d_in[3];

    float* outp = nullptr;
    float* attp = nullptr;
    long long os = (long long)out_size;
    if (os >= OUT_ELEMS + ATT_ELEMS) {
        outp = (float*)d_out;
        attp = (float*)d_out + OUT_ELEMS;
    } else if (os >= ATT_ELEMS) {
        attp = (float*)d_out;
    } else {
        outp = (float*)d_out;
    }

    cvt_all<<<QKV_BLOCKS + MBIT_BLOCKS, 256>>>(Q, K, V, M);

    cudaFuncSetAttribute(attn_p1, cudaFuncAttributeMaxDynamicSharedMemorySize, SMEM_P1);
    cudaFuncSetAttribute(attn_p2, cudaFuncAttributeMaxDynamicSharedMemorySize, SMEM_P2);
    dim3 grid(Ss / QT, BH);
    attn_p1<<<grid, NTH, SMEM_P1>>>();
    attn_p2<<<grid, NTH, SMEM_P2>>>(outp, attp);
}